// round 16
// baseline (speedup 1.0000x reference)
#include <cuda_runtime.h>
#include <cuda_bf16.h>
#include <math.h>
#include <stdint.h>

#define D        2048
#define NEXP     64
#define BM       128
#define KC       128
#define NCHUNK   (D / KC)     // 16
#define NTHR     256
#define LG_STRIDE 66

// smem layout (bytes) — bf16 tiles, rows are 256 B (128 bf16)
// A per (buf,split): 128 rows x 128 bf16 = 32768 B ; B per (buf,split): 64 x 128 bf16 = 16384 B
#define A_TILE   32768
#define B_TILE   16384
#define OFF_A    0
#define OFF_B    (4 * A_TILE)             // 131072
#define OFF_PSUM (OFF_B + 4 * B_TILE)     // 196608
#define OFF_S1   (OFF_PSUM + 256)
#define OFF_S2   (OFF_S1 + 512)
#define SMEM_TOTAL (OFF_S2 + 512)         // 197888

// named barriers: FULL(buf)=1+buf, EMPTY(buf)=3+buf
#define BAR_SYNC(id)   asm volatile("bar.sync %0, %1;"   :: "r"(id), "n"(NTHR) : "memory")
#define BAR_ARRIVE(id) asm volatile("bar.arrive %0, %1;" :: "r"(id), "n"(NTHR) : "memory")

// Prototype bf16 splits, swizzled per chunk: [chunk][split][n][16 granules]
__device__ __align__(16) unsigned char g_pb[NCHUNK * 2 * B_TILE];   // 512 KB
__device__ float g_psum[NEXP];
__device__ float g_pinv[NEXP];

// ---------------- PTX helpers (baseline, no 'a' features) ----------------
__device__ __forceinline__ uint32_t cvta_s(const void* p) {
    uint32_t a;
    asm("{ .reg .u64 t; cvta.to.shared.u64 t, %1; cvt.u32.u64 %0, t; }" : "=r"(a) : "l"(p));
    return a;
}
__device__ __forceinline__ void cp16(uint32_t dst, const void* src) {
    asm volatile("cp.async.ca.shared.global [%0], [%1], 16;" :: "r"(dst), "l"(src));
}
#define CP_COMMIT() asm volatile("cp.async.commit_group;")
#define CP_WAIT0()  asm volatile("cp.async.wait_group 0;")

#define LDSM4(R, addr) asm volatile( \
    "ldmatrix.sync.aligned.m8n8.x4.shared.b16 {%0,%1,%2,%3}, [%4];" \
    : "=r"((R)[0]), "=r"((R)[1]), "=r"((R)[2]), "=r"((R)[3]) : "r"(addr))

// bf16 m16n8k16, fp32 accumulate (non-volatile: pure register op)
#define MMA(Cf, A_, B0_, B1_) asm( \
    "mma.sync.aligned.m16n8k16.row.col.f32.bf16.bf16.f32 " \
    "{%0,%1,%2,%3}, {%4,%5,%6,%7}, {%8,%9}, {%0,%1,%2,%3};" \
    : "+f"((Cf)[0]), "+f"((Cf)[1]), "+f"((Cf)[2]), "+f"((Cf)[3]) \
    : "r"((A_)[0]), "r"((A_)[1]), "r"((A_)[2]), "r"((A_)[3]), \
      "r"(B0_), "r"(B1_))

__device__ __forceinline__ uint32_t pack_bf2(__nv_bfloat16 lo, __nv_bfloat16 hi) {
    __nv_bfloat162 t = __halves2bfloat162(lo, hi);
    return *(uint32_t*)&t;
}

// ---------------------------------------------------------------------------
// Kernel 1a: per-expert inv-norm + psum (one reduction pass).
// ---------------------------------------------------------------------------
__global__ __launch_bounds__(256) void proto_norm_kernel(const float* __restrict__ p) {
    const int e = blockIdx.x;
    const int t = threadIdx.x;
    const float* row = p + (size_t)e * D;

    __shared__ float r1[256], r2[256];

    float ss = 0.f, sm = 0.f;
    for (int i = t; i < D; i += 256) {
        float v = row[i];
        ss = fmaf(v, v, ss);
        sm += v;
    }
    r1[t] = ss; r2[t] = sm;
    __syncthreads();
    for (int s = 128; s > 0; s >>= 1) {
        if (t < s) { r1[t] += r1[t + s]; r2[t] += r2[t + s]; }
        __syncthreads();
    }
    if (t == 0) {
        const float inv = 1.f / fmaxf(sqrtf(r1[0]), 1e-8f);
        g_pinv[e] = inv;
        g_psum[e] = r2[0] * inv;
    }
}

// ---------------------------------------------------------------------------
// Kernel 1b: wide split+swizzle scatter. 512 CTAs (8 per expert).
// ---------------------------------------------------------------------------
__global__ __launch_bounds__(256) void proto_split_kernel(const float* __restrict__ p) {
    const int e     = blockIdx.x >> 3;
    const int slice = blockIdx.x & 7;          // 256-element slice of the row
    const int t     = threadIdx.x;
    const float inv = g_pinv[e];
    const int i = slice * 256 + t;             // element index in row

    float v = p[(size_t)e * D + i] * inv;
    __nv_bfloat16 b1 = __float2bfloat16_rn(v);
    __nv_bfloat16 b2 = __float2bfloat16_rn(v - __bfloat162float(b1));
    const int ch = i >> 7;                      // chunk of 128
    const int k  = i & 127;
    const uint32_t sw = (uint32_t)((((k >> 3) ^ (e & 7)) << 4) + (k & 7) * 2);
    unsigned char* base = g_pb + (size_t)ch * (2 * B_TILE) + e * 256;
    *(__nv_bfloat16*)(base + sw)          = b1;
    *(__nv_bfloat16*)(base + B_TILE + sw) = b2;
}

// ---------------------------------------------------------------------------
// Kernel 2: warp-specialized bf16 mma.sync router, KC=128 (16 rendezvous).
//   warps 0-3: consumers (m32n64 each); warps 4-7: producers.
// ---------------------------------------------------------------------------
__global__ __launch_bounds__(NTHR, 1) void router_kernel(
    const float* __restrict__ x,
    float* __restrict__ out_w,
    float* __restrict__ out_i,
    int write_idx)
{
    extern __shared__ __align__(16) unsigned char smem[];
    float* sP  = (float*)(smem + OFF_PSUM);
    float* s1s = (float*)(smem + OFF_S1);
    float* s2s = (float*)(smem + OFF_S2);

    const int tid  = threadIdx.x;
    const int lane = tid & 31;
    const int warp = tid >> 5;
    const int tokBase = blockIdx.x * BM;

    if (tid < NEXP) sP[tid] = g_psum[tid];

    if (warp >= 4) {
        // ================= PRODUCER =================
        const int m = tid - 128;                   // token row 0..127
        const float* xrow = x + (size_t)(tokBase + m) * D;
        const int xm7 = m & 7;
        const uint32_t sB_u32 = cvta_s(smem + OFF_B);
        float s1 = 0.f, s2 = 0.f;

        for (int c = 0; c < NCHUNK; c++) {
            const int buf = c & 1;
            if (c >= 2) BAR_SYNC(3 + buf);         // wait EMPTY(buf)

            // B cp.async: chunk c (32 KB = 2048 granules / 128 thr = 16 each)
            {
                const unsigned char* src = g_pb + (size_t)c * (2 * B_TILE);
                const uint32_t dstb = sB_u32 + buf * (2 * B_TILE);
#pragma unroll
                for (int i = 0; i < 16; i++) {
                    const int j = m + i * 128;
                    cp16(dstb + j * 16, src + j * 16);
                }
                CP_COMMIT();
            }
            // x LDG + bf16 2-way split + STS, in two 64-float halves
            uint4* a1p = (uint4*)(smem + OFF_A + buf * (2 * A_TILE) + m * 256);
            uint4* a2p = (uint4*)((unsigned char*)a1p + A_TILE);
#pragma unroll
            for (int half = 0; half < 2; half++) {
                float4 xr[16];
                const float4* xs = (const float4*)(xrow + c * KC + half * 64);
#pragma unroll
                for (int g = 0; g < 16; g++) xr[g] = xs[g];
                const float* xv = (const float*)xr;
#pragma unroll
                for (int h = 0; h < 8; h++) {
                    __nv_bfloat16 b[8], cres[8];
#pragma unroll
                    for (int j = 0; j < 8; j++) {
                        float v = xv[h * 8 + j];
                        s1 += v;
                        s2 = fmaf(v, v, s2);
                        b[j]    = __float2bfloat16_rn(v);
                        cres[j] = __float2bfloat16_rn(v - __bfloat162float(b[j]));
                    }
                    uint4 u1, u2;
                    u1.x = pack_bf2(b[0], b[1]); u1.y = pack_bf2(b[2], b[3]);
                    u1.z = pack_bf2(b[4], b[5]); u1.w = pack_bf2(b[6], b[7]);
                    u2.x = pack_bf2(cres[0], cres[1]); u2.y = pack_bf2(cres[2], cres[3]);
                    u2.z = pack_bf2(cres[4], cres[5]); u2.w = pack_bf2(cres[6], cres[7]);
                    const int cc = (half * 8 + h) ^ xm7;
                    a1p[cc] = u1;
                    a2p[cc] = u2;
                }
            }
            CP_WAIT0();
            BAR_ARRIVE(1 + buf);                   // signal FULL(buf)
        }
        s1s[m] = s1;
        s2s[m] = s2;
    } else {
        // ================= CONSUMER: m32n64, bf16 k16, 8 s-steps =================
        const uint32_t sA_u32 = cvta_s(smem + OFF_A);
        const uint32_t sB_u32 = cvta_s(smem + OFF_B);
        const int lx7 = lane & 7;

        // rows are 256 B now
        const uint32_t aRowByte = (uint32_t)(warp * 32 + lx7 + ((lane >> 3) & 1) * 8) * 256;
        const int aCB = lane >> 4;
        const uint32_t bRowByte = (uint32_t)(lx7 + (lane >> 4) * 8) * 256;
        const int bCB = (lane >> 3) & 1;

        float C[16][4];
#pragma unroll
        for (int f = 0; f < 16; f++) { C[f][0] = C[f][1] = C[f][2] = C[f][3] = 0.f; }

        for (int c = 0; c < NCHUNK; c++) {
            const int buf = c & 1;
            BAR_SYNC(1 + buf);                     // wait FULL(buf)

            const uint32_t A1b = sA_u32 + buf * (2 * A_TILE) + aRowByte;
            const uint32_t A2b = A1b + A_TILE;
            const uint32_t B1b = sB_u32 + buf * (2 * B_TILE) + bRowByte;
            const uint32_t B2b = B1b + B_TILE;

#pragma unroll
            for (int s = 0; s < 8; s++) {          // k16 steps: 8 per 128-K chunk
                // granule index 0..15; XOR affects low 3 bits only (bank group)
                const uint32_t ac = (uint32_t)(((2 * s + aCB) ^ lx7) * 16);
                const uint32_t bc = (uint32_t)(((2 * s + bCB) ^ lx7) * 16);

                uint32_t a1[2][4], a2[2][4];
                LDSM4(a1[0], A1b + ac);
                LDSM4(a1[1], A1b + 4096 + ac);     // +16 rows (16*256)
                LDSM4(a2[0], A2b + ac);
                LDSM4(a2[1], A2b + 4096 + ac);
                uint32_t B1[4][4], B2[4][4];
#pragma unroll
                for (int p = 0; p < 4; p++) {
                    LDSM4(B1[p], B1b + p * 4096 + bc);   // 16 experts per p (16*256)
                    LDSM4(B2[p], B2b + p * 4096 + bc);
                }

                // 4 product rounds x 16 independent accumulators
#pragma unroll
                for (int mt = 0; mt < 2; mt++)
#pragma unroll
                    for (int p = 0; p < 4; p++) {
                        MMA(C[mt * 8 + 2 * p],     a1[mt], B1[p][0], B1[p][1]);  // b1*b1'
                        MMA(C[mt * 8 + 2 * p + 1], a1[mt], B1[p][2], B1[p][3]);
                    }
#pragma unroll
                for (int mt = 0; mt < 2; mt++)
#pragma unroll
                    for (int p = 0; p < 4; p++) {
                        MMA(C[mt * 8 + 2 * p],     a1[mt], B2[p][0], B2[p][1]);  // b1*b2'
                        MMA(C[mt * 8 + 2 * p + 1], a1[mt], B2[p][2], B2[p][3]);
                    }
#pragma unroll
                for (int mt = 0; mt < 2; mt++)
#pragma unroll
                    for (int p = 0; p < 4; p++) {
                        MMA(C[mt * 8 + 2 * p],     a2[mt], B1[p][0], B1[p][1]);  // b2*b1'
                        MMA(C[mt * 8 + 2 * p + 1], a2[mt], B1[p][2], B1[p][3]);
                    }
#pragma unroll
                for (int mt = 0; mt < 2; mt++)
#pragma unroll
                    for (int p = 0; p < 4; p++) {
                        MMA(C[mt * 8 + 2 * p],     a2[mt], B2[p][0], B2[p][1]);  // b2*b2'
                        MMA(C[mt * 8 + 2 * p + 1], a2[mt], B2[p][2], B2[p][3]);
                    }
            }

            BAR_ARRIVE(3 + buf);                   // signal EMPTY(buf)
        }

        // park accumulators until everyone is past the buffers
        __syncthreads();

        const int np = lane >> 2;
        const int kq = lane & 3;
        float* lg = (float*)smem;
#pragma unroll
        for (int mt = 0; mt < 2; mt++)
#pragma unroll
            for (int nt = 0; nt < 8; nt++) {
                const int row = warp * 32 + mt * 16 + np;
                const int col = nt * 8 + 2 * kq;
                *(float2*)(lg + row * LG_STRIDE + col) =
                    make_float2(C[mt * 8 + nt][0], C[mt * 8 + nt][1]);
                *(float2*)(lg + (row + 8) * LG_STRIDE + col) =
                    make_float2(C[mt * 8 + nt][2], C[mt * 8 + nt][3]);
            }
    }

    // producers fall through to here; consumers hit it inside their branch
    if (warp >= 4) __syncthreads();
    __syncthreads();

    // ---- epilogue: thread t < 128 = token t ----
    if (tid < BM) {
        const int m = tid;
        const float* lg = (const float*)smem;
        const float S1 = s1s[m];
        const float S2 = s2s[m];
        const float mu   = S1 * (1.f / D);
        const float var  = S2 * (1.f / D) - mu * mu;
        const float rinv = rsqrtf(var + 1e-5f) * 0.125f;   // fold 1/TEMP

        const float* lrow = lg + m * LG_STRIDE;
        float best1 = -1e30f, best2 = -1e30f;
        int i1 = 0, i2 = 0;
#pragma unroll 8
        for (int e = 0; e < NEXP; e++) {
            float l = (lrow[e] - mu * sP[e]) * rinv;
            if (l > best1)      { best2 = best1; i2 = i1; best1 = l; i1 = e; }
            else if (l > best2) { best2 = l; i2 = e; }
        }
        float ed = expf(best2 - best1);
        float w1 = 1.f / (1.f + ed);
        float w2 = ed / (1.f + ed);

        const int tg = tokBase + m;
        out_w[tg * 2 + 0] = w1;
        out_w[tg * 2 + 1] = w2;
        if (write_idx) {
            out_i[tg * 2 + 0] = (float)i1;
            out_i[tg * 2 + 1] = (float)i2;
        }
    }
}

// ---------------------------------------------------------------------------
extern "C" void kernel_launch(void* const* d_in, const int* in_sizes, int n_in,
                              void* d_out, int out_size) {
    const float* x = (const float*)d_in[0];   // [4,4096,2048] f32
    const float* p = (const float*)d_in[1];   // [64,2048] f32
    float* out = (float*)d_out;

    const int ntok = in_sizes[0] / D;         // 16384
    const int write_idx = (out_size >= 4 * ntok) ? 1 : 0;
    float* out_i = out + 2 * ntok;

    cudaFuncSetAttribute(router_kernel, cudaFuncAttributeMaxDynamicSharedMemorySize, SMEM_TOTAL);

    proto_norm_kernel<<<NEXP, 256>>>(p);
    proto_split_kernel<<<NEXP * 8, 256>>>(p);
    router_kernel<<<ntok / BM, NTHR, SMEM_TOTAL>>>(x, out, out_i, write_idx);
}

// round 17
// speedup vs baseline: 1.0495x; 1.0495x over previous
#include <cuda_runtime.h>
#include <cuda_bf16.h>
#include <math.h>
#include <stdint.h>

#define D        2048
#define NEXP     64
#define BM       128
#define KC       64
#define NCHUNK   (D / KC)     // 32
#define NTHR     256
#define LG_STRIDE 66

// smem layout (bytes) — bf16 tiles
// A per (buf,split): 128 rows x 64 bf16 = 16384 B ; B per (buf,split): 64 x 64 bf16 = 8192 B
#define A_TILE   16384
#define B_TILE   8192
#define OFF_A    0
#define OFF_B    (4 * A_TILE)             // 65536
#define OFF_PSUM (OFF_B + 4 * B_TILE)     // 98304
#define OFF_S1   (OFF_PSUM + 256)
#define OFF_S2   (OFF_S1 + 512)
#define SMEM_TOTAL (OFF_S2 + 512)         // 99328

// named barriers: FULL(buf)=1+buf, EMPTY(buf)=3+buf
#define BAR_SYNC(id)   asm volatile("bar.sync %0, %1;"   :: "r"(id), "n"(NTHR) : "memory")
#define BAR_ARRIVE(id) asm volatile("bar.arrive %0, %1;" :: "r"(id), "n"(NTHR) : "memory")

// Prototype bf16 splits, swizzled per chunk: [chunk][split][n][8 granules]
__device__ __align__(16) unsigned char g_pb[NCHUNK * 2 * B_TILE];
__device__ float g_psum[NEXP];

// ---------------- PTX helpers (baseline, no 'a' features) ----------------
__device__ __forceinline__ uint32_t cvta_s(const void* p) {
    uint32_t a;
    asm("{ .reg .u64 t; cvta.to.shared.u64 t, %1; cvt.u32.u64 %0, t; }" : "=r"(a) : "l"(p));
    return a;
}
__device__ __forceinline__ void cp16(uint32_t dst, const void* src) {
    asm volatile("cp.async.ca.shared.global [%0], [%1], 16;" :: "r"(dst), "l"(src));
}
#define CP_COMMIT() asm volatile("cp.async.commit_group;")
#define CP_WAIT0()  asm volatile("cp.async.wait_group 0;")

#define LDSM4(R, addr) asm volatile( \
    "ldmatrix.sync.aligned.m8n8.x4.shared.b16 {%0,%1,%2,%3}, [%4];" \
    : "=r"((R)[0]), "=r"((R)[1]), "=r"((R)[2]), "=r"((R)[3]) : "r"(addr))

// bf16 m16n8k16, fp32 accumulate (non-volatile: pure register op)
#define MMA(Cf, A_, B0_, B1_) asm( \
    "mma.sync.aligned.m16n8k16.row.col.f32.bf16.bf16.f32 " \
    "{%0,%1,%2,%3}, {%4,%5,%6,%7}, {%8,%9}, {%0,%1,%2,%3};" \
    : "+f"((Cf)[0]), "+f"((Cf)[1]), "+f"((Cf)[2]), "+f"((Cf)[3]) \
    : "r"((A_)[0]), "r"((A_)[1]), "r"((A_)[2]), "r"((A_)[3]), \
      "r"(B0_), "r"(B1_))

__device__ __forceinline__ uint32_t pack_bf2(__nv_bfloat16 lo, __nv_bfloat16 hi) {
    __nv_bfloat162 t = __halves2bfloat162(lo, hi);
    return *(uint32_t*)&t;
}

// ---------------------------------------------------------------------------
// Kernel 1: fused prep, 4 CTAs per expert (redundant norm, parallel scatter).
// ---------------------------------------------------------------------------
__global__ __launch_bounds__(256) void proto_prep_kernel(const float* __restrict__ p) {
    const int e = blockIdx.x >> 2;
    const int q = blockIdx.x & 3;              // quarter of the row
    const int t = threadIdx.x;
    const float* row = p + (size_t)e * D;

    __shared__ float r1[256], r2[256];

    float ss = 0.f, sm = 0.f;
    for (int i = t; i < D; i += 256) {
        float v = row[i];
        ss = fmaf(v, v, ss);
        sm += v;
    }
    r1[t] = ss; r2[t] = sm;
    __syncthreads();
    for (int s = 128; s > 0; s >>= 1) {
        if (t < s) { r1[t] += r1[t + s]; r2[t] += r2[t + s]; }
        __syncthreads();
    }
    const float inv = 1.f / fmaxf(sqrtf(r1[0]), 1e-8f);
    if (q == 0 && t == 0) g_psum[e] = r2[0] * inv;

    // scatter this CTA's 512-element quarter (2 per thread)
#pragma unroll
    for (int r = 0; r < 2; r++) {
        const int i = q * 512 + r * 256 + t;
        float v = row[i] * inv;
        __nv_bfloat16 b1 = __float2bfloat16_rn(v);
        __nv_bfloat16 b2 = __float2bfloat16_rn(v - __bfloat162float(b1));
        const int ch = i >> 6;
        const int k  = i & 63;
        const uint32_t sw = (uint32_t)((((k >> 3) ^ (e & 7)) << 4) + (k & 7) * 2);
        unsigned char* base = g_pb + (size_t)ch * (2 * B_TILE) + e * 128;
        *(__nv_bfloat16*)(base + sw)          = b1;
        *(__nv_bfloat16*)(base + B_TILE + sw) = b2;
    }
}

// ---------------------------------------------------------------------------
// Kernel 2: warp-specialized bf16 mma.sync router (identical to R15 best).
//   warps 0-3: consumers (m32n64 each); warps 4-7: producers.
// ---------------------------------------------------------------------------
__global__ __launch_bounds__(NTHR, 1) void router_kernel(
    const float* __restrict__ x,
    float* __restrict__ out_w,
    float* __restrict__ out_i,
    int write_idx)
{
    extern __shared__ __align__(16) unsigned char smem[];
    float* sP  = (float*)(smem + OFF_PSUM);
    float* s1s = (float*)(smem + OFF_S1);
    float* s2s = (float*)(smem + OFF_S2);

    const int tid  = threadIdx.x;
    const int lane = tid & 31;
    const int warp = tid >> 5;
    const int tokBase = blockIdx.x * BM;

    if (tid < NEXP) sP[tid] = g_psum[tid];

    if (warp >= 4) {
        // ================= PRODUCER =================
        const int m = tid - 128;                   // token row 0..127
        const float* xrow = x + (size_t)(tokBase + m) * D;
        const int xm7 = m & 7;
        const uint32_t sB_u32 = cvta_s(smem + OFF_B);
        float s1 = 0.f, s2 = 0.f;

        for (int c = 0; c < NCHUNK; c++) {
            const int buf = c & 1;
            if (c >= 2) BAR_SYNC(3 + buf);         // wait EMPTY(buf)

            // B cp.async: chunk c (16 KB = 1024 granules / 128 thr = 8 each)
            {
                const unsigned char* src = g_pb + (size_t)c * (2 * B_TILE);
                const uint32_t dstb = sB_u32 + buf * (2 * B_TILE);
#pragma unroll
                for (int i = 0; i < 8; i++) {
                    const int j = m + i * 128;
                    cp16(dstb + j * 16, src + j * 16);
                }
                CP_COMMIT();
            }
            // x LDG + bf16 2-way split + STS (full 64-float row -> 2x 128B rows)
            {
                float4 xr[16];
                const float4* xs = (const float4*)(xrow + c * KC);
#pragma unroll
                for (int g = 0; g < 16; g++) xr[g] = xs[g];

                uint4* a1p = (uint4*)(smem + OFF_A + buf * (2 * A_TILE) + m * 128);
                uint4* a2p = (uint4*)((unsigned char*)a1p + A_TILE);
                const float* xv = (const float*)xr;
#pragma unroll
                for (int h = 0; h < 8; h++) {
                    __nv_bfloat16 b[8], cres[8];
#pragma unroll
                    for (int j = 0; j < 8; j++) {
                        float v = xv[h * 8 + j];
                        s1 += v;
                        s2 = fmaf(v, v, s2);
                        b[j]    = __float2bfloat16_rn(v);
                        cres[j] = __float2bfloat16_rn(v - __bfloat162float(b[j]));
                    }
                    uint4 u1, u2;
                    u1.x = pack_bf2(b[0], b[1]); u1.y = pack_bf2(b[2], b[3]);
                    u1.z = pack_bf2(b[4], b[5]); u1.w = pack_bf2(b[6], b[7]);
                    u2.x = pack_bf2(cres[0], cres[1]); u2.y = pack_bf2(cres[2], cres[3]);
                    u2.z = pack_bf2(cres[4], cres[5]); u2.w = pack_bf2(cres[6], cres[7]);
                    const int cc = h ^ xm7;
                    a1p[cc] = u1;
                    a2p[cc] = u2;
                }
            }
            CP_WAIT0();
            BAR_ARRIVE(1 + buf);                   // signal FULL(buf)
        }
        s1s[m] = s1;
        s2s[m] = s2;
    } else {
        // ================= CONSUMER: m32n64, bf16 k16 =================
        const uint32_t sA_u32 = cvta_s(smem + OFF_A);
        const uint32_t sB_u32 = cvta_s(smem + OFF_B);
        const int lx7 = lane & 7;

        const uint32_t aRowByte = (uint32_t)(warp * 32 + lx7 + ((lane >> 3) & 1) * 8) * 128;
        const int aCB = lane >> 4;
        const uint32_t bRowByte = (uint32_t)(lx7 + (lane >> 4) * 8) * 128;
        const int bCB = (lane >> 3) & 1;

        float C[16][4];
#pragma unroll
        for (int f = 0; f < 16; f++) { C[f][0] = C[f][1] = C[f][2] = C[f][3] = 0.f; }

        for (int c = 0; c < NCHUNK; c++) {
            const int buf = c & 1;
            BAR_SYNC(1 + buf);                     // wait FULL(buf)

            const uint32_t A1b = sA_u32 + buf * (2 * A_TILE) + aRowByte;
            const uint32_t A2b = A1b + A_TILE;
            const uint32_t B1b = sB_u32 + buf * (2 * B_TILE) + bRowByte;
            const uint32_t B2b = B1b + B_TILE;

#pragma unroll
            for (int s = 0; s < 4; s++) {          // k16 steps: 4 per 64-K chunk
                const uint32_t ac = (uint32_t)(((2 * s + aCB) ^ lx7) * 16);
                const uint32_t bc = (uint32_t)(((2 * s + bCB) ^ lx7) * 16);

                uint32_t a1[2][4], a2[2][4];
                LDSM4(a1[0], A1b + ac);
                LDSM4(a1[1], A1b + 2048 + ac);
                LDSM4(a2[0], A2b + ac);
                LDSM4(a2[1], A2b + 2048 + ac);
                uint32_t B1[4][4], B2[4][4];
#pragma unroll
                for (int p = 0; p < 4; p++) {
                    LDSM4(B1[p], B1b + p * 2048 + bc);
                    LDSM4(B2[p], B2b + p * 2048 + bc);
                }

                // 4 product rounds x 16 independent accumulators
#pragma unroll
                for (int mt = 0; mt < 2; mt++)
#pragma unroll
                    for (int p = 0; p < 4; p++) {
                        MMA(C[mt * 8 + 2 * p],     a1[mt], B1[p][0], B1[p][1]);  // b1*b1'
                        MMA(C[mt * 8 + 2 * p + 1], a1[mt], B1[p][2], B1[p][3]);
                    }
#pragma unroll
                for (int mt = 0; mt < 2; mt++)
#pragma unroll
                    for (int p = 0; p < 4; p++) {
                        MMA(C[mt * 8 + 2 * p],     a1[mt], B2[p][0], B2[p][1]);  // b1*b2'
                        MMA(C[mt * 8 + 2 * p + 1], a1[mt], B2[p][2], B2[p][3]);
                    }
#pragma unroll
                for (int mt = 0; mt < 2; mt++)
#pragma unroll
                    for (int p = 0; p < 4; p++) {
                        MMA(C[mt * 8 + 2 * p],     a2[mt], B1[p][0], B1[p][1]);  // b2*b1'
                        MMA(C[mt * 8 + 2 * p + 1], a2[mt], B1[p][2], B1[p][3]);
                    }
#pragma unroll
                for (int mt = 0; mt < 2; mt++)
#pragma unroll
                    for (int p = 0; p < 4; p++) {
                        MMA(C[mt * 8 + 2 * p],     a2[mt], B2[p][0], B2[p][1]);  // b2*b2'
                        MMA(C[mt * 8 + 2 * p + 1], a2[mt], B2[p][2], B2[p][3]);
                    }
            }

            BAR_ARRIVE(3 + buf);                   // signal EMPTY(buf)
        }

        // park accumulators until everyone is past the buffers
        __syncthreads();

        const int np = lane >> 2;
        const int kq = lane & 3;
        float* lg = (float*)smem;
#pragma unroll
        for (int mt = 0; mt < 2; mt++)
#pragma unroll
            for (int nt = 0; nt < 8; nt++) {
                const int row = warp * 32 + mt * 16 + np;
                const int col = nt * 8 + 2 * kq;
                *(float2*)(lg + row * LG_STRIDE + col) =
                    make_float2(C[mt * 8 + nt][0], C[mt * 8 + nt][1]);
                *(float2*)(lg + (row + 8) * LG_STRIDE + col) =
                    make_float2(C[mt * 8 + nt][2], C[mt * 8 + nt][3]);
            }
    }

    // producers fall through to here; consumers hit it inside their branch
    if (warp >= 4) __syncthreads();
    __syncthreads();

    // ---- epilogue: thread t < 128 = token t ----
    if (tid < BM) {
        const int m = tid;
        const float* lg = (const float*)smem;
        const float S1 = s1s[m];
        const float S2 = s2s[m];
        const float mu   = S1 * (1.f / D);
        const float var  = S2 * (1.f / D) - mu * mu;
        const float rinv = rsqrtf(var + 1e-5f) * 0.125f;   // fold 1/TEMP

        const float* lrow = lg + m * LG_STRIDE;
        float best1 = -1e30f, best2 = -1e30f;
        int i1 = 0, i2 = 0;
#pragma unroll 8
        for (int e = 0; e < NEXP; e++) {
            float l = (lrow[e] - mu * sP[e]) * rinv;
            if (l > best1)      { best2 = best1; i2 = i1; best1 = l; i1 = e; }
            else if (l > best2) { best2 = l; i2 = e; }
        }
        float ed = expf(best2 - best1);
        float w1 = 1.f / (1.f + ed);
        float w2 = ed / (1.f + ed);

        const int tg = tokBase + m;
        out_w[tg * 2 + 0] = w1;
        out_w[tg * 2 + 1] = w2;
        if (write_idx) {
            out_i[tg * 2 + 0] = (float)i1;
            out_i[tg * 2 + 1] = (float)i2;
        }
    }
}

// ---------------------------------------------------------------------------
extern "C" void kernel_launch(void* const* d_in, const int* in_sizes, int n_in,
                              void* d_out, int out_size) {
    const float* x = (const float*)d_in[0];   // [4,4096,2048] f32
    const float* p = (const float*)d_in[1];   // [64,2048] f32
    float* out = (float*)d_out;

    const int ntok = in_sizes[0] / D;         // 16384
    const int write_idx = (out_size >= 4 * ntok) ? 1 : 0;
    float* out_i = out + 2 * ntok;

    cudaFuncSetAttribute(router_kernel, cudaFuncAttributeMaxDynamicSharedMemorySize, SMEM_TOTAL);

    proto_prep_kernel<<<NEXP * 4, 256>>>(p);
    router_kernel<<<ntok / BM, NTHR, SMEM_TOTAL>>>(x, out, out_i, write_idx);
}